// round 2
// baseline (speedup 1.0000x reference)
#include <cuda_runtime.h>
#include <math_constants.h>

// SPP: out = concat(x, pool5(x), pool9(x), pool13(x)) along channels.
// Uses the SPPF cascade identity: pool9 = pool5(pool5), pool13 = pool5(pool9),
// each pool5 done separably (horizontal via warp shuffles, vertical via smem).
//
// x: (32, 512, 32, 32) f32.  out: (32, 2048, 32, 32) f32.
// One block per (n, c) plane; 1024 threads, warp == image row.

#define NCHAN 512
#define HW 1024          // 32*32
#define PLANES (32 * 512)

__global__ __launch_bounds__(1024, 2)
void spp_kernel(const float* __restrict__ x, float* __restrict__ out) {
    // 36 rows: rows 0,1 and 34,35 are permanent -INF pads; data in rows 2..33.
    __shared__ float s[36][32];

    const int xc   = threadIdx.x;        // column 0..31 (lane)
    const int yr   = threadIdx.y;        // row 0..31 (warp)
    const int tid  = yr * 32 + xc;
    const int plane = blockIdx.x;        // n*512 + c
    const int n = plane >> 9;
    const int c = plane & (NCHAN - 1);

    // Load this thread's pixel and pass through to output section 0.
    const float* __restrict__ xin = x + (size_t)plane * HW;
    float v = xin[tid];

    float* __restrict__ ob = out + ((size_t)n * (4 * NCHAN) + c) * HW + tid;
    ob[0] = v;

    // Initialize the 4 pad rows once (they are never overwritten).
    if (tid < 128) {
        int r  = tid >> 5;                   // 0..3
        int cc = tid & 31;
        int row = (r < 2) ? r : (32 + r);    // 0, 1, 34, 35
        s[row][cc] = -CUDART_INF_F;
    }

    const unsigned FULL = 0xffffffffu;

    #pragma unroll
    for (int p = 0; p < 3; ++p) {
        // ---- horizontal 5-max in registers (shfl OOB returns own value:
        //      max(v, v) is a no-op, so edges are handled for free) ----
        float l1 = __shfl_up_sync  (FULL, v, 1);
        float l2 = __shfl_up_sync  (FULL, v, 2);
        float r1 = __shfl_down_sync(FULL, v, 1);
        float r2 = __shfl_down_sync(FULL, v, 2);
        float h = fmaxf(fmaxf(fmaxf(l1, l2), fmaxf(r1, r2)), v);

        // need pads valid + previous iteration's readers done
        s[yr + 2][xc] = h;
        __syncthreads();

        // ---- vertical 5-max from smem (pitch 32: lane x -> bank x, clean) ----
        float m0 = s[yr    ][xc];
        float m1 = s[yr + 1][xc];
        float m2 = s[yr + 2][xc];
        float m3 = s[yr + 3][xc];
        float m4 = s[yr + 4][xc];
        v = fmaxf(fmaxf(fmaxf(m0, m1), fmaxf(m2, m3)), m4);

        // sections 1..3 of the channel concat
        ob[(size_t)(p + 1) * NCHAN * HW] = v;

        __syncthreads();  // protect smem before next pool overwrites it
    }
}

extern "C" void kernel_launch(void* const* d_in, const int* in_sizes, int n_in,
                              void* d_out, int out_size) {
    const float* x = (const float*)d_in[0];
    float* out     = (float*)d_out;
    dim3 blk(32, 32);
    spp_kernel<<<PLANES, blk>>>(x, out);
}

// round 3
// speedup vs baseline: 1.8028x; 1.8028x over previous
#include <cuda_runtime.h>
#include <math_constants.h>

// SPP: out = concat(x, pool5(x), pool9(x), pool13(x)) along channels.
// Cascade identity: pool9 = pool5(pool5(x)), pool13 = pool5(pool9(x)).
// One WARP per (n,c) 32x32 plane. lane = x column; the lane's entire 32-row
// column lives in registers. Horizontal 5-max via 4 warp shuffles per row
// (OOB shfl returns own value -> free edge handling under max). Vertical
// 5-max via a 5-deep register ring (-INF boundary rows). Zero shared memory,
// zero __syncthreads.
//
// x: (32, 512, 32, 32) f32 -> out: (32, 2048, 32, 32) f32.

#define NCHAN 512
#define HW 1024
#define PLANES (32 * 512)
#define WARPS_PER_BLK 8

__global__ __launch_bounds__(32 * WARPS_PER_BLK)
void spp_kernel(const float* __restrict__ x, float* __restrict__ out) {
    const int lane  = threadIdx.x & 31;
    const int wid   = threadIdx.x >> 5;
    const int plane = blockIdx.x * WARPS_PER_BLK + wid;   // n*512 + c

    const int n = plane >> 9;
    const int c = plane & (NCHAN - 1);

    const float* __restrict__ xin = x + (size_t)plane * HW + lane;
    float* __restrict__ ob = out + ((size_t)n * (4 * NCHAN) + c) * HW + lane;

    // Load the lane's column (32 coalesced 128B row-loads per warp, huge MLP).
    float v[32];
    #pragma unroll
    for (int y = 0; y < 32; ++y) v[y] = xin[y * 32];

    // Pass-through section 0 of the channel concat.
    #pragma unroll
    for (int y = 0; y < 32; ++y) ob[y * 32] = v[y];

    const unsigned FULL = 0xffffffffu;

    #pragma unroll
    for (int p = 0; p < 3; ++p) {
        float* __restrict__ obp = ob + (size_t)(p + 1) * NCHAN * HW;

        // h-row ring: r0 = h[y-4] ... r3 = h[y-1]; -INF = top padding.
        float r0 = -CUDART_INF_F, r1 = -CUDART_INF_F,
              r2 = -CUDART_INF_F, r3 = -CUDART_INF_F;

        #pragma unroll
        for (int y = 0; y < 34; ++y) {
            float h;
            if (y < 32) {
                // Horizontal 5-max in registers via shuffles.
                float val = v[y];
                float l1 = __shfl_up_sync  (FULL, val, 1);
                float l2 = __shfl_up_sync  (FULL, val, 2);
                float d1 = __shfl_down_sync(FULL, val, 1);
                float d2 = __shfl_down_sync(FULL, val, 2);
                h = fmaxf(fmaxf(fmaxf(l1, l2), fmaxf(d1, d2)), val);
            } else {
                h = -CUDART_INF_F;   // bottom padding rows
            }

            if (y >= 2) {
                // Output row (y-2) = max over h[y-4 .. y].
                float m = fmaxf(fmaxf(fmaxf(r0, r1), fmaxf(r2, r3)), h);
                v[y - 2] = m;                 // in-place: feeds next pool
                obp[(y - 2) * 32] = m;
            }

            r0 = r1; r1 = r2; r2 = r3; r3 = h;   // renamed away by unroll
        }
    }
}

extern "C" void kernel_launch(void* const* d_in, const int* in_sizes, int n_in,
                              void* d_out, int out_size) {
    const float* x = (const float*)d_in[0];
    float* out     = (float*)d_out;
    spp_kernel<<<PLANES / WARPS_PER_BLK, 32 * WARPS_PER_BLK>>>(x, out);
}